// round 7
// baseline (speedup 1.0000x reference)
#include <cuda_runtime.h>
#include <math.h>

// ---------------------------------------------------------------------------
// EncoderGRUODE: B=256, T=512, D_IN=64, H=128
// 128 CTAs x 512 threads. Thread (z = tid>>7, i = tid&127): element i, k-quarter
// [32z, 32z+32). All dot products use packed fp32x2 FMA (FFMA2 via PTX).
// W_node + W_ih in registers; W_hh in SMEM; W_out streamed from L2.
// ---------------------------------------------------------------------------

#define B_   256
#define T_   512
#define DIN  64
#define H_   128

typedef unsigned long long ull;

// packed weights produced by prep_kernel
__device__ float4 g_whh4[12288];   // [0:4096) R, [4096:8192) Z, [8192:12288) N ; idx=(k/4)*128+i
__device__ float4 g_wout4[2048];   // idx = (k/4)*64 + j  -> {W_out[j][k..k+3]}
__device__ int    g_mask[T_];
__device__ float  g_dt[T_];

// ---------------------------------------------------------------------------
__global__ void prep_kernel(const float* __restrict__ W_hh,
                            const float* __restrict__ W_out,
                            const unsigned char* __restrict__ mask_raw,
                            const float* __restrict__ tp)
{
    int gtid = blockIdx.x * blockDim.x + threadIdx.x;
    int nthr = gridDim.x * blockDim.x;

    for (int idx = gtid; idx < 4096; idx += nthr) {
        int kq = idx >> 7, i = idx & 127, k = kq * 4;
        g_whh4[idx] = make_float4(W_hh[i * H_ + k],     W_hh[i * H_ + k + 1],
                                  W_hh[i * H_ + k + 2], W_hh[i * H_ + k + 3]);
        int iz = H_ + i;
        g_whh4[4096 + idx] = make_float4(W_hh[iz * H_ + k],     W_hh[iz * H_ + k + 1],
                                         W_hh[iz * H_ + k + 2], W_hh[iz * H_ + k + 3]);
        int in_ = 2 * H_ + i;
        g_whh4[8192 + idx] = make_float4(W_hh[in_ * H_ + k],     W_hh[in_ * H_ + k + 1],
                                         W_hh[in_ * H_ + k + 2], W_hh[in_ * H_ + k + 3]);
    }
    for (int idx = gtid; idx < 2048; idx += nthr) {
        int kq = idx >> 6, j = idx & 63, k = kq * 4;
        g_wout4[idx] = make_float4(W_out[j * H_ + k],     W_out[j * H_ + k + 1],
                                   W_out[j * H_ + k + 2], W_out[j * H_ + k + 3]);
    }
    if (gtid < T_)
        g_dt[gtid] = (gtid == 0) ? 0.01f : (tp[gtid] - tp[gtid - 1]);

    // robust mask decode (uint8 / int32 / float32) — unchanged (passed R5/R6)
    if (blockIdx.x == 0 && threadIdx.x == 0) {
        bool nz_nonmult = false, one_mult = false, f32_sig = true;
        for (int i = 0; i < T_; i++) {
            unsigned char v = mask_raw[i];
            int m4 = i & 3;
            if (m4 != 0 && v) nz_nonmult = true;
            if (m4 == 0 && v == 1) one_mult = true;
            if (m4 == 0 || m4 == 1) { if (v != 0) f32_sig = false; }
            else if (m4 == 2)       { if (v != 0 && v != 0x80) f32_sig = false; }
            else                    { if (v != 0 && v != 0x3F) f32_sig = false; }
        }
        if (!nz_nonmult && one_mult) {
            const int* mi = (const int*)mask_raw;
            for (int i = 0; i < T_; i++) g_mask[i] = (mi[i] != 0);
        } else if (nz_nonmult && f32_sig) {
            const float* mf = (const float*)mask_raw;
            for (int i = 0; i < T_; i++) g_mask[i] = (mf[i] != 0.0f);
        } else {
            for (int i = 0; i < T_; i++) g_mask[i] = (mask_raw[i] != 0);
        }
    }
}

// ---------------------------------------------------------------------------
// SMEM layout (float offsets)
#define SMF_WHH  0        // 49152 floats (R|Z|N, float4 idx=(k/4)*128+i per gate)
#define SMF_S    49152    // 256: state s[row*128 + k]
#define SMF_HO   49408    // 256: h_ode [row*128 + k]
#define SMF_XK   49664    // 1024: RK4 partials xk[row*512 + z*128 + i]
#define SMF_XO   49664    // 512: out-proj partials (aliases XK; disjoint lifetime)
#define SMF_IG   50688    // 3072: i-gate partials [(g*2+row)*512 + z*128 + i]
#define SMF_WH   53760    // 3072: W_hh partials  [(g*2+row)*512 + z*128 + i]
#define SMF_INP  56832    // 128: inp [row*64 + j]
#define SMF_PO   56960    // 128: prev_out [row*64 + j]
#define SMF_TOT  57088
#define SMEM_BYTES (SMF_TOT * 4)   // 228352 B <= 232448 max dynamic

__device__ __forceinline__ void fma2(ull& acc, ull a, ull b) {
    asm("fma.rn.f32x2 %0, %1, %2, %0;" : "+l"(acc) : "l"(a), "l"(b));
}
__device__ __forceinline__ float psum(ull a) {
    float2 f = *reinterpret_cast<float2*>(&a);
    return f.x + f.y;
}
__device__ __forceinline__ float tanh_fast(float x) {
    float y;
    asm("tanh.approx.f32 %0, %1;" : "=f"(y) : "f"(x));
    return y;
}

__global__ void __launch_bounds__(512, 1)
enc_gruode_kernel(const float* __restrict__ x,
                  const float* __restrict__ W_ih,
                  const float* __restrict__ b_ih,
                  const float* __restrict__ b_hh,
                  const float* __restrict__ W_node,
                  const float* __restrict__ b_node,
                  const float* __restrict__ b_out,
                  float* __restrict__ out)
{
    extern __shared__ float sm[];
    const int tid = threadIdx.x;
    const int i   = tid & 127;
    const int z   = tid >> 7;

    // ---- stage packed W_hh into SMEM ----
    {
        float4* d = (float4*)sm;
        for (int idx = tid; idx < 12288; idx += 512) d[idx] = g_whh4[idx];
    }
    if (tid < 256) sm[SMF_S + tid] = 0.0f;
    if (tid < 128) sm[SMF_PO + tid] = b_out[tid & 63];  // prev_out at t=0 (h0=0)

    // ---- register weights (k-pair packed as ull) ----
    ull wn2[16];   // W_node[i][32z .. +32)
    {
        const ulonglong2* ws = (const ulonglong2*)(W_node + (size_t)i * H_ + 32 * z);
#pragma unroll
        for (int q = 0; q < 8; q++) { ulonglong2 v = ws[q]; wn2[2*q] = v.x; wn2[2*q+1] = v.y; }
    }
    ull wr2[8], wz2[8], wm2[8];   // W_ih rows r,z,n over k in [16z, 16z+16)
    {
        const ulonglong2* sr = (const ulonglong2*)(W_ih + (size_t)i * DIN + 16 * z);
        const ulonglong2* sz = (const ulonglong2*)(W_ih + (size_t)(H_ + i) * DIN + 16 * z);
        const ulonglong2* sn = (const ulonglong2*)(W_ih + (size_t)(2 * H_ + i) * DIN + 16 * z);
#pragma unroll
        for (int q = 0; q < 4; q++) {
            ulonglong2 a = sr[q]; wr2[2*q] = a.x; wr2[2*q+1] = a.y;
            ulonglong2 b = sz[q]; wz2[2*q] = b.x; wz2[2*q+1] = b.y;
            ulonglong2 c = sn[q]; wm2[2*q] = c.x; wm2[2*q+1] = c.y;
        }
    }

    // ---- combiner-only registers (threads tid<256: row = z) ----
    float bn_i = 0.f, bs_r = 0.f, bs_z = 0.f, bihn = 0.f, bhhn = 0.f, bo = 0.f;
    if (tid < 256) {
        bn_i = b_node[i];
        bs_r = b_ih[i]        + b_hh[i];
        bs_z = b_ih[128 + i]  + b_hh[128 + i];
        bihn = b_ih[256 + i];
        bhhn = b_hh[256 + i];
    }
    if (tid < 128) bo = b_out[i & 63];

    // pointers (tid<128 threads use xr/orow; row/j folded in)
    const float* xr   = x   + (size_t)(2 * blockIdx.x + (i >> 6)) * T_ * DIN + (i & 63);
    float*       orow = out + (size_t)(2 * blockIdx.x + (i >> 6)) * T_ * DIN + (i & 63);

    __syncthreads();

    const ulonglong2* U  = (const ulonglong2*)(sm + SMF_S + 32 * z);         // row0 state quarter
    const ulonglong2* V  = (const ulonglong2*)(sm + SMF_S + 128 + 32 * z);   // row1
    const ulonglong2* HU = (const ulonglong2*)(sm + SMF_HO + 32 * z);
    const ulonglong2* HV = (const ulonglong2*)(sm + SMF_HO + 128 + 32 * z);
    const ulonglong2* IU = (const ulonglong2*)(sm + SMF_INP + 16 * z);
    const ulonglong2* IV = (const ulonglong2*)(sm + SMF_INP + 64 + 16 * z);
    const ulonglong2* W2 = (const ulonglong2*)sm;                            // W_hh base
    const ulonglong2* WO = (const ulonglong2*)g_wout4;

    float hreg = 0.f, ksum = 0.f, hode = 0.f;

    // one RK4 matvec partial over my quarter, both rows -> XK
#define STAGE_PARTIAL()                                                     \
    {                                                                       \
        ull a0 = 0, a1 = 0, c0 = 0, c1 = 0;                                 \
        _Pragma("unroll")                                                   \
        for (int q = 0; q < 8; q++) {                                       \
            ulonglong2 u = U[q], v = V[q];                                  \
            fma2(a0, wn2[2*q], u.x); fma2(a1, wn2[2*q+1], u.y);             \
            fma2(c0, wn2[2*q], v.x); fma2(c1, wn2[2*q+1], v.y);             \
        }                                                                   \
        sm[SMF_XK + z * 128 + i]       = psum(a0) + psum(a1);               \
        sm[SMF_XK + 512 + z * 128 + i] = psum(c0) + psum(c1);               \
    }

    for (int t = 0; t < T_; ++t) {
        const float dt  = g_dt[t];
        const int   msk = g_mask[t];
        const float hdt = 0.5f * dt;

        float xv = 0.f;
        if (tid < 128) xv = msk ? xr[(size_t)t * DIN] : sm[SMF_PO + tid];

        // ---------------- RK4 stage 1 ----------------
        STAGE_PARTIAL();
        if (tid < 128) sm[SMF_INP + tid] = xv;
        __syncthreads();                                                   // B1
        if (tid < 256) {
            float s4 = sm[SMF_XK + z * 512 + i]       + sm[SMF_XK + z * 512 + 128 + i]
                     + sm[SMF_XK + z * 512 + 256 + i] + sm[SMF_XK + z * 512 + 384 + i];
            float kv = tanh_fast(s4 + bn_i);
            ksum = kv;
            sm[SMF_S + z * 128 + i] = fmaf(hdt, kv, hreg);
        }
        __syncthreads();                                                   // B2

        // ---------------- i-gate partials (independent; uses INP) ------
        {
            ull ar = 0, az = 0, an = 0, br = 0, bz = 0, bn2 = 0;
#pragma unroll
            for (int q = 0; q < 4; q++) {
                ulonglong2 u = IU[q], v = IV[q];
                fma2(ar, wr2[2*q], u.x); fma2(ar, wr2[2*q+1], u.y);
                fma2(az, wz2[2*q], u.x); fma2(az, wz2[2*q+1], u.y);
                fma2(an, wm2[2*q], u.x); fma2(an, wm2[2*q+1], u.y);
                fma2(br, wr2[2*q], v.x); fma2(br, wr2[2*q+1], v.y);
                fma2(bz, wz2[2*q], v.x); fma2(bz, wz2[2*q+1], v.y);
                fma2(bn2, wm2[2*q], v.x); fma2(bn2, wm2[2*q+1], v.y);
            }
            sm[SMF_IG + 0 * 512 + z * 128 + i] = psum(ar);
            sm[SMF_IG + 1 * 512 + z * 128 + i] = psum(br);
            sm[SMF_IG + 2 * 512 + z * 128 + i] = psum(az);
            sm[SMF_IG + 3 * 512 + z * 128 + i] = psum(bz);
            sm[SMF_IG + 4 * 512 + z * 128 + i] = psum(an);
            sm[SMF_IG + 5 * 512 + z * 128 + i] = psum(bn2);
        }

        // ---------------- RK4 stage 2 ----------------
        STAGE_PARTIAL();
        __syncthreads();                                                   // B3
        if (tid < 256) {
            float s4 = sm[SMF_XK + z * 512 + i]       + sm[SMF_XK + z * 512 + 128 + i]
                     + sm[SMF_XK + z * 512 + 256 + i] + sm[SMF_XK + z * 512 + 384 + i];
            float kv = tanh_fast(s4 + bn_i);
            ksum = fmaf(2.0f, kv, ksum);
            sm[SMF_S + z * 128 + i] = fmaf(hdt, kv, hreg);
        }
        __syncthreads();                                                   // B4

        // ---------------- RK4 stage 3 ----------------
        STAGE_PARTIAL();
        __syncthreads();                                                   // B5
        if (tid < 256) {
            float s4 = sm[SMF_XK + z * 512 + i]       + sm[SMF_XK + z * 512 + 128 + i]
                     + sm[SMF_XK + z * 512 + 256 + i] + sm[SMF_XK + z * 512 + 384 + i];
            float kv = tanh_fast(s4 + bn_i);
            ksum = fmaf(2.0f, kv, ksum);
            sm[SMF_S + z * 128 + i] = fmaf(dt, kv, hreg);
        }
        __syncthreads();                                                   // B6

        // ---------------- RK4 stage 4 ----------------
        STAGE_PARTIAL();
        __syncthreads();                                                   // B7
        if (tid < 256) {
            float s4 = sm[SMF_XK + z * 512 + i]       + sm[SMF_XK + z * 512 + 128 + i]
                     + sm[SMF_XK + z * 512 + 256 + i] + sm[SMF_XK + z * 512 + 384 + i];
            float kv = tanh_fast(s4 + bn_i);
            hode = fmaf(dt * (1.0f / 6.0f), ksum + kv, hreg);
            sm[SMF_HO + z * 128 + i] = hode;
        }
        __syncthreads();                                                   // B8

        // ---------------- GRU: W_hh partials (both rows, my quarter) ----
        {
            ull R0 = 0, R1 = 0, Z0 = 0, Z1 = 0, N0 = 0, N1 = 0;
#pragma unroll
            for (int q = 0; q < 8; q++) {
                const size_t kq = (size_t)(8 * z + q) * 128 + i;
                ulonglong2 wr = W2[kq];
                ulonglong2 wz = W2[4096 + kq];
                ulonglong2 wn = W2[8192 + kq];
                ulonglong2 u = HU[q], v = HV[q];
                fma2(R0, wr.x, u.x); fma2(R0, wr.y, u.y);
                fma2(R1, wr.x, v.x); fma2(R1, wr.y, v.y);
                fma2(Z0, wz.x, u.x); fma2(Z0, wz.y, u.y);
                fma2(Z1, wz.x, v.x); fma2(Z1, wz.y, v.y);
                fma2(N0, wn.x, u.x); fma2(N0, wn.y, u.y);
                fma2(N1, wn.x, v.x); fma2(N1, wn.y, v.y);
            }
            sm[SMF_WH + 0 * 512 + z * 128 + i] = psum(R0);
            sm[SMF_WH + 1 * 512 + z * 128 + i] = psum(R1);
            sm[SMF_WH + 2 * 512 + z * 128 + i] = psum(Z0);
            sm[SMF_WH + 3 * 512 + z * 128 + i] = psum(Z1);
            sm[SMF_WH + 4 * 512 + z * 128 + i] = psum(N0);
            sm[SMF_WH + 5 * 512 + z * 128 + i] = psum(N1);
        }
        __syncthreads();                                                   // B9

        // ---------------- gate combine (row = z, tid < 256) -------------
        if (tid < 256) {
            int br_ = SMF_IG + (0 * 2 + z) * 512 + i;
            float irT = sm[br_] + sm[br_ + 128] + sm[br_ + 256] + sm[br_ + 384];
            br_ = SMF_IG + (1 * 2 + z) * 512 + i;
            float izT = sm[br_] + sm[br_ + 128] + sm[br_ + 256] + sm[br_ + 384];
            br_ = SMF_IG + (2 * 2 + z) * 512 + i;
            float inT = sm[br_] + sm[br_ + 128] + sm[br_ + 256] + sm[br_ + 384];
            br_ = SMF_WH + (0 * 2 + z) * 512 + i;
            float hrT = sm[br_] + sm[br_ + 128] + sm[br_ + 256] + sm[br_ + 384];
            br_ = SMF_WH + (1 * 2 + z) * 512 + i;
            float hzT = sm[br_] + sm[br_ + 128] + sm[br_ + 256] + sm[br_ + 384];
            br_ = SMF_WH + (2 * 2 + z) * 512 + i;
            float hnT = sm[br_] + sm[br_ + 128] + sm[br_ + 256] + sm[br_ + 384];

            float rr = 1.0f / (1.0f + expf(-(irT + hrT + bs_r)));
            float zz = 1.0f / (1.0f + expf(-(izT + hzT + bs_z)));
            float nn = tanhf(inT + bihn + rr * (hnT + bhhn));
            hreg = nn + zz * (hode - nn);
            sm[SMF_S + z * 128 + i] = hreg;
        }
        __syncthreads();                                                   // B10

        // ---------------- output projection (also next prev_out) --------
        {
            const int row = i >> 6, j = i & 63;
            const ulonglong2* HS = (const ulonglong2*)(sm + SMF_S + row * 128 + 32 * z);
            ull a = 0, b = 0;
#pragma unroll
            for (int q = 0; q < 8; q++) {
                ulonglong2 w = WO[(size_t)(8 * z + q) * 64 + j];
                ulonglong2 u = HS[q];
                fma2(a, w.x, u.x);
                fma2(b, w.y, u.y);
            }
            sm[SMF_XO + z * 128 + i] = psum(a) + psum(b);
        }
        __syncthreads();                                                   // B11
        if (tid < 128) {
            float y = sm[SMF_XO + i]       + sm[SMF_XO + 128 + i]
                    + sm[SMF_XO + 256 + i] + sm[SMF_XO + 384 + i] + bo;
            orow[(size_t)t * DIN] = y;
            sm[SMF_PO + i] = y;
        }
        __syncthreads();                                                   // B12
    }
#undef STAGE_PARTIAL
}

// ---------------------------------------------------------------------------
extern "C" void kernel_launch(void* const* d_in, const int* in_sizes, int n_in,
                              void* d_out, int out_size)
{
    const float*         x      = (const float*)d_in[0];
    const float*         tp     = (const float*)d_in[1];
    const unsigned char* mask   = (const unsigned char*)d_in[2];
    const float*         W_ih   = (const float*)d_in[3];
    const float*         W_hh   = (const float*)d_in[4];
    const float*         b_ih   = (const float*)d_in[5];
    const float*         b_hh   = (const float*)d_in[6];
    const float*         W_node = (const float*)d_in[7];
    const float*         b_node = (const float*)d_in[8];
    const float*         W_out  = (const float*)d_in[9];
    const float*         b_out  = (const float*)d_in[10];
    float*               out    = (float*)d_out;

    prep_kernel<<<32, 256>>>(W_hh, W_out, mask, tp);

    cudaFuncSetAttribute(enc_gruode_kernel,
                         cudaFuncAttributeMaxDynamicSharedMemorySize,
                         SMEM_BYTES);
    enc_gruode_kernel<<<B_ / 2, 512, SMEM_BYTES>>>(
        x, W_ih, b_ih, b_hh, W_node, b_node, b_out, out);
}

// round 8
// speedup vs baseline: 1.2041x; 1.2041x over previous
#include <cuda_runtime.h>
#include <math.h>

// ---------------------------------------------------------------------------
// EncoderGRUODE: B=256, T=512, D_IN=64, H=128
// 128 CTAs x 256 threads. Thread (half = lane>>4, i = 16*warp + (lane&15)):
// owns element i of row `half`, computes k-half `half` of every dot.
// Half-exchange via shfl_xor(16). All dots use fma.rn.f32x2 (FFMA2).
// 6 barriers/step via double-buffered RK4 state.
// ---------------------------------------------------------------------------

#define B_   256
#define T_   512
#define DIN  64
#define H_   128

typedef unsigned long long ull;

// packed weights produced by prep_kernel
__device__ float4 g_whh4[12288];   // [0:4096) R | [4096:8192) Z | [8192:12288) N ; idx=(k/4)*128+i
__device__ float4 g_wout4[2048];   // idx=(k/4)*64+j -> {W_out[j][k..k+3]}
__device__ int    g_mask[T_];
__device__ float  g_dt[T_];

// ---------------------------------------------------------------------------
__global__ void prep_kernel(const float* __restrict__ W_hh,
                            const float* __restrict__ W_out,
                            const unsigned char* __restrict__ mask_raw,
                            const float* __restrict__ tp)
{
    int gtid = blockIdx.x * blockDim.x + threadIdx.x;
    int nthr = gridDim.x * blockDim.x;

    for (int idx = gtid; idx < 4096; idx += nthr) {
        int kq = idx >> 7, i = idx & 127, k = kq * 4;
        g_whh4[idx] = make_float4(W_hh[i * H_ + k],     W_hh[i * H_ + k + 1],
                                  W_hh[i * H_ + k + 2], W_hh[i * H_ + k + 3]);
        int iz = H_ + i;
        g_whh4[4096 + idx] = make_float4(W_hh[iz * H_ + k],     W_hh[iz * H_ + k + 1],
                                         W_hh[iz * H_ + k + 2], W_hh[iz * H_ + k + 3]);
        int in_ = 2 * H_ + i;
        g_whh4[8192 + idx] = make_float4(W_hh[in_ * H_ + k],     W_hh[in_ * H_ + k + 1],
                                         W_hh[in_ * H_ + k + 2], W_hh[in_ * H_ + k + 3]);
    }
    for (int idx = gtid; idx < 2048; idx += nthr) {
        int kq = idx >> 6, j = idx & 63, k = kq * 4;
        g_wout4[idx] = make_float4(W_out[j * H_ + k],     W_out[j * H_ + k + 1],
                                   W_out[j * H_ + k + 2], W_out[j * H_ + k + 3]);
    }
    if (gtid < T_)
        g_dt[gtid] = (gtid == 0) ? 0.01f : (tp[gtid] - tp[gtid - 1]);

    // robust mask decode (uint8 / int32 / float32) — unchanged (passed R5-R7)
    if (blockIdx.x == 0 && threadIdx.x == 0) {
        bool nz_nonmult = false, one_mult = false, f32_sig = true;
        for (int i = 0; i < T_; i++) {
            unsigned char v = mask_raw[i];
            int m4 = i & 3;
            if (m4 != 0 && v) nz_nonmult = true;
            if (m4 == 0 && v == 1) one_mult = true;
            if (m4 == 0 || m4 == 1) { if (v != 0) f32_sig = false; }
            else if (m4 == 2)       { if (v != 0 && v != 0x80) f32_sig = false; }
            else                    { if (v != 0 && v != 0x3F) f32_sig = false; }
        }
        if (!nz_nonmult && one_mult) {
            const int* mi = (const int*)mask_raw;
            for (int i = 0; i < T_; i++) g_mask[i] = (mi[i] != 0);
        } else if (nz_nonmult && f32_sig) {
            const float* mf = (const float*)mask_raw;
            for (int i = 0; i < T_; i++) g_mask[i] = (mf[i] != 0.0f);
        } else {
            for (int i = 0; i < T_; i++) g_mask[i] = (mask_raw[i] != 0);
        }
    }
}

// ---------------------------------------------------------------------------
// SMEM layout (float offsets). Row stride 132 on state buffers kills write
// conflicts between the two 16-lane half groups of a warp.
#define RS       132
#define SMF_WHH  0        // 49152 floats (R|Z|N as float4, idx=(k/4)*128+i)
#define SMF_A    49152    // 264: h      [row*RS + k]
#define SMF_B    49416    // 264: RK4 scratch
#define SMF_C    49680    // 264: RK4 scratch
#define SMF_HO   49944    // 264: h_ode
#define SMF_INP  50208    // 136: inp [row*68 + j]
#define SMF_PO   50344    // 128: prev_out [row*64 + j]
#define SMF_XO   50472    // 512: out-proj partials [row*256 + kq*64 + j]
#define SMF_DT   50984    // 512
#define SMF_MSK  51496    // 512 (ints)
#define SMF_TOT  52008
#define SMEM_BYTES (SMF_TOT * 4)   // 208032 B

__device__ __forceinline__ void fma2(ull& acc, ull a, ull b) {
    asm("fma.rn.f32x2 %0, %1, %2, %0;" : "+l"(acc) : "l"(a), "l"(b));
}
__device__ __forceinline__ float psum(ull a) {
    float2 f = *reinterpret_cast<float2*>(&a);
    return f.x + f.y;
}
__device__ __forceinline__ float tanh_fast(float x) {
    float y;
    asm("tanh.approx.f32 %0, %1;" : "=f"(y) : "f"(x));
    return y;
}
__device__ __forceinline__ float sig_fast(float x) {
    return fmaf(0.5f, tanh_fast(0.5f * x), 0.5f);
}

__global__ void __launch_bounds__(256, 1)
enc_gruode_kernel(const float* __restrict__ x,
                  const float* __restrict__ W_ih,
                  const float* __restrict__ b_ih,
                  const float* __restrict__ b_hh,
                  const float* __restrict__ W_node,
                  const float* __restrict__ b_node,
                  const float* __restrict__ b_out,
                  float* __restrict__ out)
{
    extern __shared__ float sm[];
    int* smi = (int*)sm;
    const int tid  = threadIdx.x;
    const int lane = tid & 31;
    const int wrp  = tid >> 5;
    const int half = lane >> 4;                 // k-half AND my row
    const int i    = (wrp << 4) | (lane & 15);  // my element

    // ---- stage packed W_hh into SMEM ----
    {
        float4* d = (float4*)sm;
        for (int idx = tid; idx < 12288; idx += 256) d[idx] = g_whh4[idx];
    }
    for (int idx = tid; idx < 512; idx += 256) {
        sm[SMF_DT + idx]   = g_dt[idx];
        smi[SMF_MSK + idx] = g_mask[idx];
    }
    for (int idx = tid; idx < 264; idx += 256) sm[SMF_A + idx] = 0.0f;
    if (tid < 128) sm[SMF_PO + tid] = b_out[tid & 63];   // prev_out at t=0 (h0=0)

    // ---- register weights, k-pair packed as ull ----
    ull wn2[32];                     // W_node[i][64*half .. +64)
    {
        const ulonglong2* ws = (const ulonglong2*)(W_node + (size_t)i * H_ + 64 * half);
#pragma unroll
        for (int q = 0; q < 16; q++) { ulonglong2 v = ws[q]; wn2[2*q] = v.x; wn2[2*q+1] = v.y; }
    }
    ull wr2[16], wz2[16], wm2[16];   // W_ih rows r,z,n over k in [32*half, +32)
    {
        const ulonglong2* sr = (const ulonglong2*)(W_ih + (size_t)i * DIN + 32 * half);
        const ulonglong2* sz = (const ulonglong2*)(W_ih + (size_t)(H_ + i) * DIN + 32 * half);
        const ulonglong2* sn = (const ulonglong2*)(W_ih + (size_t)(2 * H_ + i) * DIN + 32 * half);
#pragma unroll
        for (int q = 0; q < 8; q++) {
            ulonglong2 a = sr[q]; wr2[2*q] = a.x; wr2[2*q+1] = a.y;
            ulonglong2 b = sz[q]; wz2[2*q] = b.x; wz2[2*q+1] = b.y;
            ulonglong2 c = sn[q]; wm2[2*q] = c.x; wm2[2*q+1] = c.y;
        }
    }

    // combiner constants (every thread is the combiner for (row=half, elem=i))
    const float bn_i = b_node[i];
    const float bs_r = b_ih[i]       + b_hh[i];
    const float bs_z = b_ih[128 + i] + b_hh[128 + i];
    const float bihn = b_ih[256 + i];
    const float bhhn = b_hh[256 + i];
    const float bo   = (tid < 128) ? b_out[tid & 63] : 0.0f;

    // x / out pointers for the tid<128 role (row = tid>>6, j = tid&63)
    const float* xr   = x   + (size_t)(2 * blockIdx.x + (tid >> 6)) * T_ * DIN + (tid & 63);
    float*       orow = out + (size_t)(2 * blockIdx.x + (tid >> 6)) * T_ * DIN + (tid & 63);

    __syncthreads();

    float hreg = 0.0f;
    float xv = (tid < 128) ? __ldg(xr) : 0.0f;   // prefetch x[t=0]

    // one RK4 matvec: full dot for my row via half-dot + shfl_xor(16)
    auto STAGE = [&](const float* buf) -> float {
        const ulonglong2* U = (const ulonglong2*)(buf + 64 * half);
        const ulonglong2* V = (const ulonglong2*)(buf + RS + 64 * half);
        ull a0 = 0, a1 = 0, c0 = 0, c1 = 0;
#pragma unroll
        for (int q = 0; q < 16; q++) {
            ulonglong2 u = U[q], v = V[q];
            fma2(a0, wn2[2*q], u.x); fma2(a1, wn2[2*q+1], u.y);
            fma2(c0, wn2[2*q], v.x); fma2(c1, wn2[2*q+1], v.y);
        }
        float p0 = psum(a0) + psum(a1);          // row0 partial, my k-half
        float p1 = psum(c0) + psum(c1);          // row1 partial
        float mine = half ? p1 : p0;
        float oth  = __shfl_xor_sync(0xffffffffu, half ? p0 : p1, 16);
        return mine + oth + bn_i;
    };

    for (int t = 0; t < T_; ++t) {
        const float dt  = sm[SMF_DT + t];
        const int   msk = smi[SMF_MSK + t];
        const float hdt = 0.5f * dt;

        // ---- RK4 stage 1: read A -> write B ----
        float kv = tanh_fast(STAGE(sm + SMF_A));
        float ksum = kv;
        sm[SMF_B + half * RS + i] = fmaf(hdt, kv, hreg);
        __syncthreads();                                             // B1

        // input staging (PO ordered by B1); prefetch next x
        if (tid < 128) {
            sm[SMF_INP + (tid >> 6) * 68 + (tid & 63)] = msk ? xv : sm[SMF_PO + tid];
            if (t + 1 < T_) xv = __ldg(xr + (size_t)(t + 1) * DIN);
        }

        // ---- RK4 stage 2: read B -> write C ----
        kv = tanh_fast(STAGE(sm + SMF_B));
        ksum = fmaf(2.0f, kv, ksum);
        sm[SMF_C + half * RS + i] = fmaf(hdt, kv, hreg);
        __syncthreads();                                             // B2

        // ---- i-gate partials (INP visible post-B2), results kept in regs ----
        float irT, izT, inT;
        {
            const ulonglong2* IU = (const ulonglong2*)(sm + SMF_INP + 32 * half);
            const ulonglong2* IV = (const ulonglong2*)(sm + SMF_INP + 68 + 32 * half);
            ull ar = 0, az = 0, an = 0, br = 0, bz = 0, bn2 = 0;
#pragma unroll
            for (int q = 0; q < 8; q++) {
                ulonglong2 u = IU[q], v = IV[q];
                fma2(ar, wr2[2*q], u.x); fma2(ar, wr2[2*q+1], u.y);
                fma2(az, wz2[2*q], u.x); fma2(az, wz2[2*q+1], u.y);
                fma2(an, wm2[2*q], u.x); fma2(an, wm2[2*q+1], u.y);
                fma2(br, wr2[2*q], v.x); fma2(br, wr2[2*q+1], v.y);
                fma2(bz, wz2[2*q], v.x); fma2(bz, wz2[2*q+1], v.y);
                fma2(bn2, wm2[2*q], v.x); fma2(bn2, wm2[2*q+1], v.y);
            }
            float r0 = psum(ar), r1 = psum(br);
            float z0 = psum(az), z1 = psum(bz);
            float n0 = psum(an), n1 = psum(bn2);
            irT = (half ? r1 : r0) + __shfl_xor_sync(0xffffffffu, half ? r0 : r1, 16);
            izT = (half ? z1 : z0) + __shfl_xor_sync(0xffffffffu, half ? z0 : z1, 16);
            inT = (half ? n1 : n0) + __shfl_xor_sync(0xffffffffu, half ? n0 : n1, 16);
        }

        // ---- RK4 stage 3: read C -> write B ----
        kv = tanh_fast(STAGE(sm + SMF_C));
        ksum = fmaf(2.0f, kv, ksum);
        sm[SMF_B + half * RS + i] = fmaf(dt, kv, hreg);
        __syncthreads();                                             // B3

        // ---- RK4 stage 4: read B -> h_ode ----
        kv = tanh_fast(STAGE(sm + SMF_B));
        const float hode = fmaf(dt * (1.0f / 6.0f), ksum + kv, hreg);
        sm[SMF_HO + half * RS + i] = hode;
        __syncthreads();                                             // B4

        // ---- GRU W_hh partials (SMEM weights) + gate combine ----
        {
            const ulonglong2* HU = (const ulonglong2*)(sm + SMF_HO + 64 * half);
            const ulonglong2* HV = (const ulonglong2*)(sm + SMF_HO + RS + 64 * half);
            const ulonglong2* W2 = (const ulonglong2*)sm;
            ull R0 = 0, R1 = 0, Z0 = 0, Z1 = 0, N0 = 0, N1 = 0;
#pragma unroll
            for (int q = 0; q < 16; q++) {
                const int idx = (16 * half + q) * 128 + i;
                ulonglong2 wr = W2[idx];
                ulonglong2 wz = W2[4096 + idx];
                ulonglong2 wn = W2[8192 + idx];
                ulonglong2 u = HU[q], v = HV[q];
                fma2(R0, wr.x, u.x); fma2(R0, wr.y, u.y);
                fma2(R1, wr.x, v.x); fma2(R1, wr.y, v.y);
                fma2(Z0, wz.x, u.x); fma2(Z0, wz.y, u.y);
                fma2(Z1, wz.x, v.x); fma2(Z1, wz.y, v.y);
                fma2(N0, wn.x, u.x); fma2(N0, wn.y, u.y);
                fma2(N1, wn.x, v.x); fma2(N1, wn.y, v.y);
            }
            float r0 = psum(R0), r1 = psum(R1);
            float z0 = psum(Z0), z1 = psum(Z1);
            float n0 = psum(N0), n1 = psum(N1);
            float hrT = (half ? r1 : r0) + __shfl_xor_sync(0xffffffffu, half ? r0 : r1, 16);
            float hzT = (half ? z1 : z0) + __shfl_xor_sync(0xffffffffu, half ? z0 : z1, 16);
            float hnT = (half ? n1 : n0) + __shfl_xor_sync(0xffffffffu, half ? n0 : n1, 16);

            float rr = sig_fast(irT + hrT + bs_r);
            float zz = sig_fast(izT + hzT + bs_z);
            float nn = tanhf(inT + bihn + rr * (hnT + bhhn));
            hreg = nn + zz * (hode - nn);
            sm[SMF_A + half * RS + i] = hreg;
        }
        __syncthreads();                                             // B5

        // ---- output projection partials: j = i&63, k-quarter kq, BOTH rows ----
        {
            const int j = i & 63, kq = (i >> 6) | (half << 1);
            const ulonglong2* S0 = (const ulonglong2*)(sm + SMF_A + 32 * kq);
            const ulonglong2* S1 = (const ulonglong2*)(sm + SMF_A + RS + 32 * kq);
            const ulonglong2* WOg = (const ulonglong2*)g_wout4;
            ull o0 = 0, o1 = 0;
#pragma unroll
            for (int q = 0; q < 8; q++) {
                ulonglong2 w = WOg[(size_t)(8 * kq + q) * 64 + j];
                ulonglong2 s0 = S0[q], s1 = S1[q];
                fma2(o0, w.x, s0.x); fma2(o0, w.y, s0.y);
                fma2(o1, w.x, s1.x); fma2(o1, w.y, s1.y);
            }
            sm[SMF_XO + kq * 64 + j]       = psum(o0);
            sm[SMF_XO + 256 + kq * 64 + j] = psum(o1);
        }
        __syncthreads();                                             // B6

        // ---- output combine (also next step's prev_out); no trailing barrier:
        //      next B1 orders PO writes against next step's PO reads.
        if (tid < 128) {
            const int base = SMF_XO + (tid >> 6) * 256 + (tid & 63);
            float y = sm[base] + sm[base + 64] + sm[base + 128] + sm[base + 192] + bo;
            orow[(size_t)t * DIN] = y;
            sm[SMF_PO + tid] = y;
        }
    }
}

// ---------------------------------------------------------------------------
extern "C" void kernel_launch(void* const* d_in, const int* in_sizes, int n_in,
                              void* d_out, int out_size)
{
    const float*         x      = (const float*)d_in[0];
    const float*         tp     = (const float*)d_in[1];
    const unsigned char* mask   = (const unsigned char*)d_in[2];
    const float*         W_ih   = (const float*)d_in[3];
    const float*         W_hh   = (const float*)d_in[4];
    const float*         b_ih   = (const float*)d_in[5];
    const float*         b_hh   = (const float*)d_in[6];
    const float*         W_node = (const float*)d_in[7];
    const float*         b_node = (const float*)d_in[8];
    const float*         W_out  = (const float*)d_in[9];
    const float*         b_out  = (const float*)d_in[10];
    float*               out    = (float*)d_out;

    prep_kernel<<<32, 256>>>(W_hh, W_out, mask, tp);

    cudaFuncSetAttribute(enc_gruode_kernel,
                         cudaFuncAttributeMaxDynamicSharedMemorySize,
                         SMEM_BYTES);
    enc_gruode_kernel<<<B_ / 2, 256, SMEM_BYTES>>>(
        x, W_ih, b_ih, b_hh, W_node, b_node, b_out, out);
}